// round 7
// baseline (speedup 1.0000x reference)
#include <cuda_runtime.h>
#include <cstdint>

#define NN   50000
#define DIN  96
#define DOUT 128
#define NE   800000
#define NB   49              // ceil(NN/1024)
#define NT64 782             // ceil(NN/64) row-tiles
#define NU   (NT64 * 2)      // units: tile x col-half

// ---------------- device scratch (no allocs allowed) ----------------
__device__ __align__(16) float g_agg[NN * DIN];
__device__ int g_cnt[NN];        // zeroed at end of agg for next replay
__device__ int g_rowstart[NN];
__device__ int g_cursor[NN];
__device__ int g_bsum[NB];
__device__ int g_boff[NB];
__device__ int g_sync;           // ticket for fused scan; reset by last block
__device__ int g_csr[NE];

// ---------------------------------------------------------------------------
// K1: in-degree counts, 4 edges/thread (g_cnt pre-zeroed by prior agg run)
// ---------------------------------------------------------------------------
__global__ void count_kernel(const int* __restrict__ ei) {
    int t = blockIdx.x * blockDim.x + threadIdx.x;
    if (t < NE / 4) {
        int4 d = ((const int4*)(ei + NE))[t];
        atomicAdd(&g_cnt[d.x], 1);
        atomicAdd(&g_cnt[d.y], 1);
        atomicAdd(&g_cnt[d.z], 1);
        atomicAdd(&g_cnt[d.w], 1);
    }
}

// ---------------------------------------------------------------------------
// K2: fused two-level exclusive scan (last-block ticket does top level)
// ---------------------------------------------------------------------------
__global__ void __launch_bounds__(1024) scanAB_kernel() {
    __shared__ int wsum[32];
    __shared__ int sticket;
    int tid = threadIdx.x, lane = tid & 31, wid = tid >> 5;
    int i = blockIdx.x * 1024 + tid;
    int v = (i < NN) ? g_cnt[i] : 0;
    int s = v;
    #pragma unroll
    for (int o = 1; o < 32; o <<= 1) {
        int t = __shfl_up_sync(0xffffffffu, s, o);
        if (lane >= o) s += t;
    }
    if (lane == 31) wsum[wid] = s;
    __syncthreads();
    if (wid == 0) {
        int ws = wsum[lane];
        #pragma unroll
        for (int o = 1; o < 32; o <<= 1) {
            int t = __shfl_up_sync(0xffffffffu, ws, o);
            if (lane >= o) ws += t;
        }
        wsum[lane] = ws;
    }
    __syncthreads();
    int excl = ((wid == 0) ? 0 : wsum[wid - 1]) + s - v;
    if (i < NN) { g_rowstart[i] = excl; g_cursor[i] = excl; }
    if (tid == 0) {
        g_bsum[blockIdx.x] = wsum[31];
        __threadfence();
        sticket = atomicAdd(&g_sync, 1);
    }
    __syncthreads();
    if (sticket == NB - 1) {
        __threadfence();
        if (tid < 32) {
            volatile int* vb = g_bsum;
            int v0 = (tid < NB) ? vb[tid] : 0;
            int v1 = (tid + 32 < NB) ? vb[tid + 32] : 0;
            int s0 = v0;
            #pragma unroll
            for (int o = 1; o < 32; o <<= 1) {
                int t = __shfl_up_sync(0xffffffffu, s0, o);
                if (tid >= o) s0 += t;
            }
            int tot0 = __shfl_sync(0xffffffffu, s0, 31);
            int s1 = v1;
            #pragma unroll
            for (int o = 1; o < 32; o <<= 1) {
                int t = __shfl_up_sync(0xffffffffu, s1, o);
                if (tid >= o) s1 += t;
            }
            if (tid < NB) g_boff[tid] = s0 - v0;
            if (tid + 32 < NB) g_boff[tid + 32] = tot0 + s1 - v1;
            if (tid == 0) g_sync = 0;   // reset ticket for next replay
        }
    }
}

// ---------------------------------------------------------------------------
// K3: fill CSR, 4 edges/thread
// ---------------------------------------------------------------------------
__global__ void fill_kernel(const int* __restrict__ ei) {
    int t = blockIdx.x * blockDim.x + threadIdx.x;
    if (t < NE / 4) {
        int4 s = ((const int4*)ei)[t];
        int4 d = ((const int4*)(ei + NE))[t];
        int p0 = atomicAdd(&g_cursor[d.x], 1);
        int p1 = atomicAdd(&g_cursor[d.y], 1);
        int p2 = atomicAdd(&g_cursor[d.z], 1);
        int p3 = atomicAdd(&g_cursor[d.w], 1);
        g_csr[p0 + g_boff[d.x >> 10]] = s.x;
        g_csr[p1 + g_boff[d.y >> 10]] = s.y;
        g_csr[p2 + g_boff[d.z >> 10]] = s.z;
        g_csr[p3 + g_boff[d.w >> 10]] = s.w;
    }
}

// ---------------------------------------------------------------------------
// K4: gather-mean. Warp per row, lanes 0..23 own one float4 each, x4 unroll.
// ---------------------------------------------------------------------------
__global__ void agg_kernel(const float* __restrict__ x) {
    int warp = (blockIdx.x * blockDim.x + threadIdx.x) >> 5;
    int lane = threadIdx.x & 31;
    if (warp >= NN) return;
    int deg = g_cnt[warp];
    if (lane == 0) g_cnt[warp] = 0;          // reset for next replay
    if (lane >= 24) return;
    int rs = g_rowstart[warp] + g_boff[warp >> 10];
    float4 a0 = make_float4(0.f, 0.f, 0.f, 0.f);
    float4 a1 = make_float4(0.f, 0.f, 0.f, 0.f);
    int j = 0;
    for (; j + 4 <= deg; j += 4) {
        int s0 = g_csr[rs + j];
        int s1 = g_csr[rs + j + 1];
        int s2 = g_csr[rs + j + 2];
        int s3 = g_csr[rs + j + 3];
        float4 v0 = ((const float4*)(x + (long)s0 * DIN))[lane];
        float4 v1 = ((const float4*)(x + (long)s1 * DIN))[lane];
        float4 v2 = ((const float4*)(x + (long)s2 * DIN))[lane];
        float4 v3 = ((const float4*)(x + (long)s3 * DIN))[lane];
        a0.x += v0.x; a0.y += v0.y; a0.z += v0.z; a0.w += v0.w;
        a1.x += v1.x; a1.y += v1.y; a1.z += v1.z; a1.w += v1.w;
        a0.x += v2.x; a0.y += v2.y; a0.z += v2.z; a0.w += v2.w;
        a1.x += v3.x; a1.y += v3.y; a1.z += v3.z; a1.w += v3.w;
    }
    for (; j < deg; j++) {
        int s0 = g_csr[rs + j];
        float4 v0 = ((const float4*)(x + (long)s0 * DIN))[lane];
        a0.x += v0.x; a0.y += v0.y; a0.z += v0.z; a0.w += v0.w;
    }
    float inv = 1.0f / (float)max(deg, 1);
    a0.x = (a0.x + a1.x) * inv;
    a0.y = (a0.y + a1.y) * inv;
    a0.z = (a0.z + a1.z) * inv;
    a0.w = (a0.w + a1.w) * inv;
    ((float4*)(g_agg + (long)warp * DIN))[lane] = a0;
}

// ---------------------------------------------------------------------------
// K5: out = relu( agg @ Wl^T + bl + x @ Wr^T )  -- packed fp32x2 FFMA.
// Unit = (64-row tile) x (64-col half). Block = 128 thr = 32 col-threads x
// 4 row-groups of 16 rows. Thread owns 2 cols x 16 rows: per k-chunk only
// 4 spread weight LDS.128 amortized over 128 FFMA2; data loads are warp
// broadcasts. Weights staged once per block (persistent, parity-stable).
// ---------------------------------------------------------------------------
__device__ __forceinline__ unsigned long long ffma2_(unsigned long long a,
                                                     unsigned long long b,
                                                     unsigned long long c) {
    unsigned long long d;
    asm("fma.rn.f32x2 %0, %1, %2, %3;" : "=l"(d) : "l"(a), "l"(b), "l"(c));
    return d;
}

#define WPAD 100
#define SM_WL 0
#define SM_WR 6400
#define SM_X  12800            // 64 rows x 96
#define SM_A  18944
#define SM_FLOATS 25088        // 100352 bytes -> 2 CTAs/SM

__global__ void __launch_bounds__(128) gemm_kernel(
    const float* __restrict__ x, const float* __restrict__ Wl,
    const float* __restrict__ bl, const float* __restrict__ Wr,
    float* __restrict__ out) {
    extern __shared__ __align__(16) float sm[];
    float* sWl = sm + SM_WL;
    float* sWr = sm + SM_WR;
    float* sx  = sm + SM_X;
    float* sa  = sm + SM_A;

    int tid = threadIdx.x;
    int colbase = (blockIdx.x & 1) * 64;   // gridDim even -> loop-invariant

    // stage this half's 64 columns of both weight matrices (padded rows)
    for (int i = tid; i < 64 * 24; i += 128) {
        int n = i / 24, q = (i - n * 24) * 4;
        *(float4*)(sWl + n * WPAD + q) = *(const float4*)(Wl + (colbase + n) * DIN + q);
        *(float4*)(sWr + n * WPAD + q) = *(const float4*)(Wr + (colbase + n) * DIN + q);
    }

    int ct = tid & 31, rg = tid >> 5;
    int c0 = ct, c1 = ct + 32;
    float b0 = __ldg(bl + colbase + c0);
    float b1 = __ldg(bl + colbase + c1);

    for (int u = blockIdx.x; u < NU; u += gridDim.x) {
        int t = u >> 1;
        __syncthreads();   // prev unit done with tiles (and weights on iter 0)
        // stage 64-row data tiles (both arrays), 1536 float4 each
        for (int i = tid; i < 64 * 24; i += 128) {
            int r = i / 24, q = i - r * 24;
            int gr = t * 64 + r; if (gr >= NN) gr = NN - 1;
            ((float4*)(sx + r * DIN))[q] = ((const float4*)(x + (long)gr * DIN))[q];
            ((float4*)(sa + r * DIN))[q] = ((const float4*)(g_agg + (long)gr * DIN))[q];
        }
        __syncthreads();

        unsigned long long acc0[16], acc1[16];
        #pragma unroll
        for (int r = 0; r < 16; r++) { acc0[r] = 0ull; acc1[r] = 0ull; }

        #pragma unroll 2
        for (int k = 0; k < DIN; k += 4) {
            ulonglong2 wl0 = *(const ulonglong2*)(sWl + c0 * WPAD + k);
            ulonglong2 wl1 = *(const ulonglong2*)(sWl + c1 * WPAD + k);
            ulonglong2 wr0 = *(const ulonglong2*)(sWr + c0 * WPAD + k);
            ulonglong2 wr1 = *(const ulonglong2*)(sWr + c1 * WPAD + k);
            #pragma unroll
            for (int r = 0; r < 16; r++) {
                int row = rg * 16 + r;
                ulonglong2 av = *(const ulonglong2*)(sa + row * DIN + k);
                ulonglong2 xv = *(const ulonglong2*)(sx + row * DIN + k);
                acc0[r] = ffma2_(wl0.x, av.x, acc0[r]);
                acc0[r] = ffma2_(wl0.y, av.y, acc0[r]);
                acc0[r] = ffma2_(wr0.x, xv.x, acc0[r]);
                acc0[r] = ffma2_(wr0.y, xv.y, acc0[r]);
                acc1[r] = ffma2_(wl1.x, av.x, acc1[r]);
                acc1[r] = ffma2_(wl1.y, av.y, acc1[r]);
                acc1[r] = ffma2_(wr1.x, xv.x, acc1[r]);
                acc1[r] = ffma2_(wr1.y, xv.y, acc1[r]);
            }
        }

        #pragma unroll
        for (int r = 0; r < 16; r++) {
            int row = t * 64 + rg * 16 + r;
            if (row < NN) {
                float l0 = __uint_as_float((unsigned)(acc0[r] & 0xffffffffull));
                float h0 = __uint_as_float((unsigned)(acc0[r] >> 32));
                float l1 = __uint_as_float((unsigned)(acc1[r] & 0xffffffffull));
                float h1 = __uint_as_float((unsigned)(acc1[r] >> 32));
                out[(long)row * DOUT + colbase + c0] = fmaxf(l0 + h0 + b0, 0.f);
                out[(long)row * DOUT + colbase + c1] = fmaxf(l1 + h1 + b1, 0.f);
            }
        }
    }
}

// ---------------------------------------------------------------------------
extern "C" void kernel_launch(void* const* d_in, const int* in_sizes, int n_in,
                              void* d_out, int out_size) {
    const float* x  = (const float*)d_in[0];
    const int*   ei = (const int*)d_in[1];
    const float* Wl = (const float*)d_in[2];
    const float* bl = (const float*)d_in[3];
    const float* Wr = (const float*)d_in[4];
    float* out = (float*)d_out;

    cudaFuncSetAttribute(gemm_kernel, cudaFuncAttributeMaxDynamicSharedMemorySize,
                         SM_FLOATS * (int)sizeof(float));

    count_kernel<<<(NE / 4 + 255) / 256, 256>>>(ei);
    scanAB_kernel<<<NB, 1024>>>();
    fill_kernel<<<(NE / 4 + 255) / 256, 256>>>(ei);
    agg_kernel<<<(NN * 32 + 255) / 256, 256>>>(x);
    gemm_kernel<<<296, 128, SM_FLOATS * sizeof(float)>>>(x, Wl, bl, Wr, out);
}

// round 8
// speedup vs baseline: 1.0173x; 1.0173x over previous
#include <cuda_runtime.h>
#include <cstdint>

#define NN   50000
#define DIN  96
#define DOUT 128
#define NE   800000
#define NB   49              // ceil(NN/1024)

// ---------------- device scratch (no allocs allowed) ----------------
__device__ __align__(16) float g_agg[NN * DIN];
__device__ int g_cnt[NN];        // zeroed at end of agg for next replay
__device__ int g_rowstart[NN];
__device__ int g_cursor[NN];
__device__ int g_bsum[NB];
__device__ int g_boff[NB];
__device__ int g_sync;           // ticket for fused scan; reset by last block
__device__ int g_csr[NE];

// ---------------------------------------------------------------------------
// K1: in-degree counts, 4 edges/thread (g_cnt pre-zeroed by prior agg run)
// ---------------------------------------------------------------------------
__global__ void count_kernel(const int* __restrict__ ei) {
    int t = blockIdx.x * blockDim.x + threadIdx.x;
    if (t < NE / 4) {
        int4 d = ((const int4*)(ei + NE))[t];
        atomicAdd(&g_cnt[d.x], 1);
        atomicAdd(&g_cnt[d.y], 1);
        atomicAdd(&g_cnt[d.z], 1);
        atomicAdd(&g_cnt[d.w], 1);
    }
}

// ---------------------------------------------------------------------------
// K2: fused two-level exclusive scan (last-block ticket does top level)
// ---------------------------------------------------------------------------
__global__ void __launch_bounds__(1024) scanAB_kernel() {
    __shared__ int wsum[32];
    __shared__ int sticket;
    int tid = threadIdx.x, lane = tid & 31, wid = tid >> 5;
    int i = blockIdx.x * 1024 + tid;
    int v = (i < NN) ? g_cnt[i] : 0;
    int s = v;
    #pragma unroll
    for (int o = 1; o < 32; o <<= 1) {
        int t = __shfl_up_sync(0xffffffffu, s, o);
        if (lane >= o) s += t;
    }
    if (lane == 31) wsum[wid] = s;
    __syncthreads();
    if (wid == 0) {
        int ws = wsum[lane];
        #pragma unroll
        for (int o = 1; o < 32; o <<= 1) {
            int t = __shfl_up_sync(0xffffffffu, ws, o);
            if (lane >= o) ws += t;
        }
        wsum[lane] = ws;
    }
    __syncthreads();
    int excl = ((wid == 0) ? 0 : wsum[wid - 1]) + s - v;
    if (i < NN) { g_rowstart[i] = excl; g_cursor[i] = excl; }
    if (tid == 0) {
        g_bsum[blockIdx.x] = wsum[31];
        __threadfence();
        sticket = atomicAdd(&g_sync, 1);
    }
    __syncthreads();
    if (sticket == NB - 1) {
        __threadfence();
        if (tid < 32) {
            volatile int* vb = g_bsum;
            int v0 = (tid < NB) ? vb[tid] : 0;
            int v1 = (tid + 32 < NB) ? vb[tid + 32] : 0;
            int s0 = v0;
            #pragma unroll
            for (int o = 1; o < 32; o <<= 1) {
                int t = __shfl_up_sync(0xffffffffu, s0, o);
                if (tid >= o) s0 += t;
            }
            int tot0 = __shfl_sync(0xffffffffu, s0, 31);
            int s1 = v1;
            #pragma unroll
            for (int o = 1; o < 32; o <<= 1) {
                int t = __shfl_up_sync(0xffffffffu, s1, o);
                if (tid >= o) s1 += t;
            }
            if (tid < NB) g_boff[tid] = s0 - v0;
            if (tid + 32 < NB) g_boff[tid + 32] = tot0 + s1 - v1;
            if (tid == 0) g_sync = 0;   // reset ticket for next replay
        }
    }
}

// ---------------------------------------------------------------------------
// K3: fill CSR, 4 edges/thread
// ---------------------------------------------------------------------------
__global__ void fill_kernel(const int* __restrict__ ei) {
    int t = blockIdx.x * blockDim.x + threadIdx.x;
    if (t < NE / 4) {
        int4 s = ((const int4*)ei)[t];
        int4 d = ((const int4*)(ei + NE))[t];
        int p0 = atomicAdd(&g_cursor[d.x], 1);
        int p1 = atomicAdd(&g_cursor[d.y], 1);
        int p2 = atomicAdd(&g_cursor[d.z], 1);
        int p3 = atomicAdd(&g_cursor[d.w], 1);
        g_csr[p0 + g_boff[d.x >> 10]] = s.x;
        g_csr[p1 + g_boff[d.y >> 10]] = s.y;
        g_csr[p2 + g_boff[d.z >> 10]] = s.z;
        g_csr[p3 + g_boff[d.w >> 10]] = s.w;
    }
}

// ---------------------------------------------------------------------------
// K4: gather-mean. Warp per row, lanes 0..23 own one float4 each, x4 unroll.
// Resets g_cnt for the next replay.
// ---------------------------------------------------------------------------
__global__ void agg_kernel(const float* __restrict__ x) {
    int warp = (blockIdx.x * blockDim.x + threadIdx.x) >> 5;
    int lane = threadIdx.x & 31;
    if (warp >= NN) return;
    int deg = g_cnt[warp];
    if (lane == 0) g_cnt[warp] = 0;          // reset for next replay
    if (lane >= 24) return;
    int rs = g_rowstart[warp] + g_boff[warp >> 10];
    float4 a0 = make_float4(0.f, 0.f, 0.f, 0.f);
    float4 a1 = make_float4(0.f, 0.f, 0.f, 0.f);
    int j = 0;
    for (; j + 4 <= deg; j += 4) {
        int s0 = g_csr[rs + j];
        int s1 = g_csr[rs + j + 1];
        int s2 = g_csr[rs + j + 2];
        int s3 = g_csr[rs + j + 3];
        float4 v0 = ((const float4*)(x + (long)s0 * DIN))[lane];
        float4 v1 = ((const float4*)(x + (long)s1 * DIN))[lane];
        float4 v2 = ((const float4*)(x + (long)s2 * DIN))[lane];
        float4 v3 = ((const float4*)(x + (long)s3 * DIN))[lane];
        a0.x += v0.x; a0.y += v0.y; a0.z += v0.z; a0.w += v0.w;
        a1.x += v1.x; a1.y += v1.y; a1.z += v1.z; a1.w += v1.w;
        a0.x += v2.x; a0.y += v2.y; a0.z += v2.z; a0.w += v2.w;
        a1.x += v3.x; a1.y += v3.y; a1.z += v3.z; a1.w += v3.w;
    }
    for (; j < deg; j++) {
        int s0 = g_csr[rs + j];
        float4 v0 = ((const float4*)(x + (long)s0 * DIN))[lane];
        a0.x += v0.x; a0.y += v0.y; a0.z += v0.z; a0.w += v0.w;
    }
    float inv = 1.0f / (float)max(deg, 1);
    a0.x = (a0.x + a1.x) * inv;
    a0.y = (a0.y + a1.y) * inv;
    a0.z = (a0.z + a1.z) * inv;
    a0.w = (a0.w + a1.w) * inv;
    ((float4*)(g_agg + (long)warp * DIN))[lane] = a0;
}

// ---------------------------------------------------------------------------
// K5: out = relu( agg @ Wl^T + bl + x @ Wr^T )   -- EXACT round-3 gemm
// (measured as part of the 126.1us config). Packed fp32x2 FFMA; block =
// 128 thr = 32 col-threads x 4 row-groups of 8; 32-row tiles; 64-col half
// per block; weights in SMEM col-major padded to 100 floats.
// ---------------------------------------------------------------------------
__device__ __forceinline__ unsigned long long ffma2_(unsigned long long a,
                                                     unsigned long long b,
                                                     unsigned long long c) {
    unsigned long long d;
    asm("fma.rn.f32x2 %0, %1, %2, %3;" : "=l"(d) : "l"(a), "l"(b), "l"(c));
    return d;
}

#define WPAD 100
#define SM_WL 0
#define SM_WR 6400
#define SM_X  12800
#define SM_A  15872
#define SM_FLOATS 18944   // 75776 bytes -> 3 CTAs/SM

__global__ void __launch_bounds__(128) gemm_kernel(
    const float* __restrict__ x, const float* __restrict__ Wl,
    const float* __restrict__ bl, const float* __restrict__ Wr,
    float* __restrict__ out) {
    extern __shared__ __align__(16) float sm[];
    float* sWl = sm + SM_WL;
    float* sWr = sm + SM_WR;
    float* sx  = sm + SM_X;
    float* sa  = sm + SM_A;

    int tid = threadIdx.x;
    int colbase = (blockIdx.x & 1) * 64;

    for (int i = tid; i < 64 * DIN; i += 128) {
        int c = i / DIN, k = i - c * DIN;
        sWl[c * WPAD + k] = Wl[(colbase + c) * DIN + k];
        sWr[c * WPAD + k] = Wr[(colbase + c) * DIN + k];
    }

    int ct = tid & 31;
    int rbase = (tid >> 5) * 8;
    int c0 = ct, c1 = ct + 32;
    float b0 = bl[colbase + c0];
    float b1 = bl[colbase + c1];

    const int NT = (NN + 31) / 32;  // 1563
    for (int t = blockIdx.x >> 1; t < NT; t += gridDim.x >> 1) {
        int row0 = t * 32;
        __syncthreads();
        for (int i = tid; i < 32 * 24; i += 128) {
            int r = i / 24, q = i - r * 24;
            int gr = row0 + r; if (gr >= NN) gr = NN - 1;
            ((float4*)(sx + r * DIN))[q] = ((const float4*)(x + (long)gr * DIN))[q];
            ((float4*)(sa + r * DIN))[q] = ((const float4*)(g_agg + (long)gr * DIN))[q];
        }
        __syncthreads();

        unsigned long long acc0[8], acc1[8];
        #pragma unroll
        for (int r = 0; r < 8; r++) { acc0[r] = 0ull; acc1[r] = 0ull; }

        #pragma unroll 4
        for (int k = 0; k < DIN; k += 4) {
            ulonglong2 wl0 = *(const ulonglong2*)(sWl + c0 * WPAD + k);
            ulonglong2 wl1 = *(const ulonglong2*)(sWl + c1 * WPAD + k);
            ulonglong2 wr0 = *(const ulonglong2*)(sWr + c0 * WPAD + k);
            ulonglong2 wr1 = *(const ulonglong2*)(sWr + c1 * WPAD + k);
            #pragma unroll
            for (int r = 0; r < 8; r++) {
                ulonglong2 av = *(const ulonglong2*)(sa + (rbase + r) * DIN + k);
                ulonglong2 xv = *(const ulonglong2*)(sx + (rbase + r) * DIN + k);
                acc0[r] = ffma2_(wl0.x, av.x, acc0[r]);
                acc0[r] = ffma2_(wl0.y, av.y, acc0[r]);
                acc0[r] = ffma2_(wr0.x, xv.x, acc0[r]);
                acc0[r] = ffma2_(wr0.y, xv.y, acc0[r]);
                acc1[r] = ffma2_(wl1.x, av.x, acc1[r]);
                acc1[r] = ffma2_(wl1.y, av.y, acc1[r]);
                acc1[r] = ffma2_(wr1.x, xv.x, acc1[r]);
                acc1[r] = ffma2_(wr1.y, xv.y, acc1[r]);
            }
        }

        #pragma unroll
        for (int r = 0; r < 8; r++) {
            int row = row0 + rbase + r;
            if (row < NN) {
                float l0 = __uint_as_float((unsigned)(acc0[r] & 0xffffffffull));
                float h0 = __uint_as_float((unsigned)(acc0[r] >> 32));
                float l1 = __uint_as_float((unsigned)(acc1[r] & 0xffffffffull));
                float h1 = __uint_as_float((unsigned)(acc1[r] >> 32));
                float v0 = l0 + h0 + b0;
                float v1 = l1 + h1 + b1;
                out[(long)row * DOUT + colbase + c0] = fmaxf(v0, 0.f);
                out[(long)row * DOUT + colbase + c1] = fmaxf(v1, 0.f);
            }
        }
    }
}

// ---------------------------------------------------------------------------
extern "C" void kernel_launch(void* const* d_in, const int* in_sizes, int n_in,
                              void* d_out, int out_size) {
    const float* x  = (const float*)d_in[0];
    const int*   ei = (const int*)d_in[1];
    const float* Wl = (const float*)d_in[2];
    const float* bl = (const float*)d_in[3];
    const float* Wr = (const float*)d_in[4];
    float* out = (float*)d_out;

    cudaFuncSetAttribute(gemm_kernel, cudaFuncAttributeMaxDynamicSharedMemorySize,
                         SM_FLOATS * (int)sizeof(float));

    count_kernel<<<(NE / 4 + 255) / 256, 256>>>(ei);
    scanAB_kernel<<<NB, 1024>>>();
    fill_kernel<<<(NE / 4 + 255) / 256, 256>>>(ei);
    agg_kernel<<<(NN * 32 + 255) / 256, 256>>>(x);
    gemm_kernel<<<444, 128, SM_FLOATS * sizeof(float)>>>(x, Wl, bl, Wr, out);
}

// round 9
// speedup vs baseline: 1.8003x; 1.7696x over previous
#include <cuda_runtime.h>
#include <cstdint>

#define NN   50000
#define DIN  96
#define DOUT 128
#define NE   800000
#define NB   49          // ceil(NN / 1024)

// Scratch (device-global: no allocations allowed)
__device__ __align__(16) float g_agg[NN * DIN];
__device__ int g_cnt[NN];
__device__ int g_rowstart[NN];   // block-local exclusive prefix
__device__ int g_cursor[NN];     // block-local cursor for fill
__device__ int g_bsum[NB];       // per-1024-block totals
__device__ int g_boff[NB];       // exclusive scan of g_bsum
__device__ int g_csr[NE];

// ---------------------------------------------------------------------------
// K1: zero counters
// ---------------------------------------------------------------------------
__global__ void zero_cnt_kernel() {
    int i = blockIdx.x * blockDim.x + threadIdx.x;
    if (i < NN) g_cnt[i] = 0;
}

// ---------------------------------------------------------------------------
// K2: in-degree counts, 4 edges/thread (int4) for atomic MLP
// ---------------------------------------------------------------------------
__global__ void count_kernel(const int* __restrict__ ei) {
    int t = blockIdx.x * blockDim.x + threadIdx.x;
    if (t < NE / 4) {
        int4 d = ((const int4*)(ei + NE))[t];
        atomicAdd(&g_cnt[d.x], 1);
        atomicAdd(&g_cnt[d.y], 1);
        atomicAdd(&g_cnt[d.z], 1);
        atomicAdd(&g_cnt[d.w], 1);
    }
}

// ---------------------------------------------------------------------------
// K3a: per-block (1024-wide) exclusive scan of counts; emit block totals
// ---------------------------------------------------------------------------
__global__ void __launch_bounds__(1024) scanA_kernel() {
    __shared__ int wsum[32];
    int tid = threadIdx.x, lane = tid & 31, wid = tid >> 5;
    int i = blockIdx.x * 1024 + tid;
    int v = (i < NN) ? g_cnt[i] : 0;
    int s = v;
    #pragma unroll
    for (int o = 1; o < 32; o <<= 1) {
        int t = __shfl_up_sync(0xffffffffu, s, o);
        if (lane >= o) s += t;
    }
    if (lane == 31) wsum[wid] = s;
    __syncthreads();
    if (wid == 0) {
        int ws = wsum[lane];
        #pragma unroll
        for (int o = 1; o < 32; o <<= 1) {
            int t = __shfl_up_sync(0xffffffffu, ws, o);
            if (lane >= o) ws += t;
        }
        wsum[lane] = ws;
    }
    __syncthreads();
    int excl = ((wid == 0) ? 0 : wsum[wid - 1]) + s - v;
    if (i < NN) { g_rowstart[i] = excl; g_cursor[i] = excl; }
    if (tid == 0) g_bsum[blockIdx.x] = wsum[31];
}

// ---------------------------------------------------------------------------
// K3b: exclusive scan of the 49 block totals (single warp, 2 elems/lane)
// ---------------------------------------------------------------------------
__global__ void scanB_kernel() {
    int lane = threadIdx.x;
    int v0 = (lane < NB) ? g_bsum[lane] : 0;
    int v1 = (lane + 32 < NB) ? g_bsum[lane + 32] : 0;
    int s0 = v0;
    #pragma unroll
    for (int o = 1; o < 32; o <<= 1) {
        int t = __shfl_up_sync(0xffffffffu, s0, o);
        if (lane >= o) s0 += t;
    }
    int tot0 = __shfl_sync(0xffffffffu, s0, 31);
    int s1 = v1;
    #pragma unroll
    for (int o = 1; o < 32; o <<= 1) {
        int t = __shfl_up_sync(0xffffffffu, s1, o);
        if (lane >= o) s1 += t;
    }
    if (lane < NB) g_boff[lane] = s0 - v0;
    if (lane + 32 < NB) g_boff[lane + 32] = tot0 + s1 - v1;
}

// ---------------------------------------------------------------------------
// K4: fill CSR, 4 edges/thread. Final slot = local cursor + block offset.
// ---------------------------------------------------------------------------
__global__ void fill_kernel(const int* __restrict__ ei) {
    int t = blockIdx.x * blockDim.x + threadIdx.x;
    if (t < NE / 4) {
        int4 s = ((const int4*)ei)[t];
        int4 d = ((const int4*)(ei + NE))[t];
        int p0 = atomicAdd(&g_cursor[d.x], 1);
        int p1 = atomicAdd(&g_cursor[d.y], 1);
        int p2 = atomicAdd(&g_cursor[d.z], 1);
        int p3 = atomicAdd(&g_cursor[d.w], 1);
        g_csr[p0 + g_boff[d.x >> 10]] = s.x;
        g_csr[p1 + g_boff[d.y >> 10]] = s.y;
        g_csr[p2 + g_boff[d.z >> 10]] = s.z;
        g_csr[p3 + g_boff[d.w >> 10]] = s.w;
    }
}

// ---------------------------------------------------------------------------
// K5: gather-mean. Warp per row, lanes 0..23 own one float4 each.
// Unrolled x4 over neighbors (8 LDG.128 in flight / warp).
// ---------------------------------------------------------------------------
__global__ void agg_kernel(const float* __restrict__ x) {
    int warp = (blockIdx.x * blockDim.x + threadIdx.x) >> 5;
    int lane = threadIdx.x & 31;
    if (warp >= NN || lane >= 24) return;
    int rs  = g_rowstart[warp] + g_boff[warp >> 10];
    int deg = g_cnt[warp];
    float4 a0 = make_float4(0.f, 0.f, 0.f, 0.f);
    float4 a1 = make_float4(0.f, 0.f, 0.f, 0.f);
    int j = 0;
    for (; j + 4 <= deg; j += 4) {
        int s0 = g_csr[rs + j];
        int s1 = g_csr[rs + j + 1];
        int s2 = g_csr[rs + j + 2];
        int s3 = g_csr[rs + j + 3];
        float4 v0 = ((const float4*)(x + (long)s0 * DIN))[lane];
        float4 v1 = ((const float4*)(x + (long)s1 * DIN))[lane];
        float4 v2 = ((const float4*)(x + (long)s2 * DIN))[lane];
        float4 v3 = ((const float4*)(x + (long)s3 * DIN))[lane];
        a0.x += v0.x; a0.y += v0.y; a0.z += v0.z; a0.w += v0.w;
        a1.x += v1.x; a1.y += v1.y; a1.z += v1.z; a1.w += v1.w;
        a0.x += v2.x; a0.y += v2.y; a0.z += v2.z; a0.w += v2.w;
        a1.x += v3.x; a1.y += v3.y; a1.z += v3.z; a1.w += v3.w;
    }
    for (; j < deg; j++) {
        int s0 = g_csr[rs + j];
        float4 v0 = ((const float4*)(x + (long)s0 * DIN))[lane];
        a0.x += v0.x; a0.y += v0.y; a0.z += v0.z; a0.w += v0.w;
    }
    float inv = 1.0f / (float)max(deg, 1);
    a0.x = (a0.x + a1.x) * inv;
    a0.y = (a0.y + a1.y) * inv;
    a0.z = (a0.z + a1.z) * inv;
    a0.w = (a0.w + a1.w) * inv;
    ((float4*)(g_agg + (long)warp * DIN))[lane] = a0;
}

// ---------------------------------------------------------------------------
// K6: out = relu( agg @ Wl^T + bl + x @ Wr^T )   (packed fp32x2 FFMA)
// ---------------------------------------------------------------------------
__device__ __forceinline__ unsigned long long ffma2_(unsigned long long a,
                                                     unsigned long long b,
                                                     unsigned long long c) {
    unsigned long long d;
    asm("fma.rn.f32x2 %0, %1, %2, %3;" : "=l"(d) : "l"(a), "l"(b), "l"(c));
    return d;
}

#define WPAD 100
#define SM_WL 0
#define SM_WR 6400
#define SM_X  12800
#define SM_A  15872
#define SM_FLOATS 18944   // 75776 bytes

__global__ void __launch_bounds__(128) gemm_kernel(
    const float* __restrict__ x, const float* __restrict__ Wl,
    const float* __restrict__ bl, const float* __restrict__ Wr,
    float* __restrict__ out) {
    extern __shared__ __align__(16) float sm[];
    float* sWl = sm + SM_WL;
    float* sWr = sm + SM_WR;
    float* sx  = sm + SM_X;
    float* sa  = sm + SM_A;

    int tid = threadIdx.x;
    int colbase = (blockIdx.x & 1) * 64;

    for (int i = tid; i < 64 * DIN; i += 128) {
        int c = i / DIN, k = i - c * DIN;
        sWl[c * WPAD + k] = Wl[(colbase + c) * DIN + k];
        sWr[c * WPAD + k] = Wr[(colbase + c) * DIN + k];
    }

    int ct = tid & 31;
    int rbase = (tid >> 5) * 8;
    int c0 = ct, c1 = ct + 32;
    float b0 = bl[colbase + c0];
    float b1 = bl[colbase + c1];

    const int NT = (NN + 31) / 32;  // 1563
    for (int t = blockIdx.x >> 1; t < NT; t += gridDim.x >> 1) {
        int row0 = t * 32;
        __syncthreads();
        for (int i = tid; i < 32 * 24; i += 128) {
            int r = i / 24, q = i - r * 24;
            int gr = row0 + r; if (gr >= NN) gr = NN - 1;
            ((float4*)(sx + r * DIN))[q] = ((const float4*)(x + (long)gr * DIN))[q];
            ((float4*)(sa + r * DIN))[q] = ((const float4*)(g_agg + (long)gr * DIN))[q];
        }
        __syncthreads();

        unsigned long long acc0[8], acc1[8];
        #pragma unroll
        for (int r = 0; r < 8; r++) { acc0[r] = 0ull; acc1[r] = 0ull; }

        #pragma unroll 4
        for (int k = 0; k < DIN; k += 4) {
            ulonglong2 wl0 = *(const ulonglong2*)(sWl + c0 * WPAD + k);
            ulonglong2 wl1 = *(const ulonglong2*)(sWl + c1 * WPAD + k);
            ulonglong2 wr0 = *(const ulonglong2*)(sWr + c0 * WPAD + k);
            ulonglong2 wr1 = *(const ulonglong2*)(sWr + c1 * WPAD + k);
            #pragma unroll
            for (int r = 0; r < 8; r++) {
                ulonglong2 av = *(const ulonglong2*)(sa + (rbase + r) * DIN + k);
                ulonglong2 xv = *(const ulonglong2*)(sx + (rbase + r) * DIN + k);
                acc0[r] = ffma2_(wl0.x, av.x, acc0[r]);
                acc0[r] = ffma2_(wl0.y, av.y, acc0[r]);
                acc0[r] = ffma2_(wr0.x, xv.x, acc0[r]);
                acc0[r] = ffma2_(wr0.y, xv.y, acc0[r]);
                acc1[r] = ffma2_(wl1.x, av.x, acc1[r]);
                acc1[r] = ffma2_(wl1.y, av.y, acc1[r]);
                acc1[r] = ffma2_(wr1.x, xv.x, acc1[r]);
                acc1[r] = ffma2_(wr1.y, xv.y, acc1[r]);
            }
        }

        #pragma unroll
        for (int r = 0; r < 8; r++) {
            int row = row0 + rbase + r;
            if (row < NN) {
                float l0 = __uint_as_float((unsigned)(acc0[r] & 0xffffffffull));
                float h0 = __uint_as_float((unsigned)(acc0[r] >> 32));
                float l1 = __uint_as_float((unsigned)(acc1[r] & 0xffffffffull));
                float h1 = __uint_as_float((unsigned)(acc1[r] >> 32));
                float v0 = l0 + h0 + b0;
                float v1 = l1 + h1 + b1;
                out[(long)row * DOUT + colbase + c0] = fmaxf(v0, 0.f);
                out[(long)row * DOUT + colbase + c1] = fmaxf(v1, 0.f);
            }
        }
    }
}

// ---------------------------------------------------------------------------
extern "C" void kernel_launch(void* const* d_in, const int* in_sizes, int n_in,
                              void* d_out, int out_size) {
    const float* x  = (const float*)d_in[0];
    const int*   ei = (const int*)d_in[1];
    const float* Wl = (const float*)d_in[2];
    const float* bl = (const float*)d_in[3];
    const float* Wr = (const float*)d_in[4];
    float* out = (float*)d_out;

    cudaFuncSetAttribute(gemm_kernel, cudaFuncAttributeMaxDynamicSharedMemorySize,
                         SM_FLOATS * (int)sizeof(float));

    zero_cnt_kernel<<<(NN + 255) / 256, 256>>>();
    count_kernel<<<(NE / 4 + 255) / 256, 256>>>(ei);
    scanA_kernel<<<NB, 1024>>>();
    scanB_kernel<<<1, 32>>>();
    fill_kernel<<<(NE / 4 + 255) / 256, 256>>>(ei);
    agg_kernel<<<(NN * 32 + 255) / 256, 256>>>(x);
    gemm_kernel<<<444, 128, SM_FLOATS * sizeof(float)>>>(x, Wl, bl, Wr, out);
}

// round 11
// speedup vs baseline: 1.8034x; 1.0018x over previous
#include <cuda_runtime.h>
#include <cstdint>

#define NN   50000
#define DIN  96
#define DOUT 128
#define NE   800000
#define NB   49          // ceil(NN / 1024)

// Scratch (device-global: no allocations allowed)
__device__ __align__(16) float g_agg[NN * DIN];
__device__ int g_cnt[NN];
__device__ int g_rowstart[NN];   // block-local exclusive prefix
__device__ int g_cursor[NN];     // block-local cursor for fill
__device__ int g_bsum[NB];       // per-1024-block totals
__device__ int g_boff[NB];       // exclusive scan of g_bsum
__device__ int g_csr[NE];

// ---------------------------------------------------------------------------
// K1: zero counters
// ---------------------------------------------------------------------------
__global__ void zero_cnt_kernel() {
    int i = blockIdx.x * blockDim.x + threadIdx.x;
    if (i < NN) g_cnt[i] = 0;
}

// ---------------------------------------------------------------------------
// K2: in-degree counts, 4 edges/thread (int4) for atomic MLP
// ---------------------------------------------------------------------------
__global__ void count_kernel(const int* __restrict__ ei) {
    int t = blockIdx.x * blockDim.x + threadIdx.x;
    if (t < NE / 4) {
        int4 d = ((const int4*)(ei + NE))[t];
        atomicAdd(&g_cnt[d.x], 1);
        atomicAdd(&g_cnt[d.y], 1);
        atomicAdd(&g_cnt[d.z], 1);
        atomicAdd(&g_cnt[d.w], 1);
    }
}

// ---------------------------------------------------------------------------
// K3a: per-block (1024-wide) exclusive scan of counts; emit block totals
// ---------------------------------------------------------------------------
__global__ void __launch_bounds__(1024) scanA_kernel() {
    __shared__ int wsum[32];
    int tid = threadIdx.x, lane = tid & 31, wid = tid >> 5;
    int i = blockIdx.x * 1024 + tid;
    int v = (i < NN) ? g_cnt[i] : 0;
    int s = v;
    #pragma unroll
    for (int o = 1; o < 32; o <<= 1) {
        int t = __shfl_up_sync(0xffffffffu, s, o);
        if (lane >= o) s += t;
    }
    if (lane == 31) wsum[wid] = s;
    __syncthreads();
    if (wid == 0) {
        int ws = wsum[lane];
        #pragma unroll
        for (int o = 1; o < 32; o <<= 1) {
            int t = __shfl_up_sync(0xffffffffu, ws, o);
            if (lane >= o) ws += t;
        }
        wsum[lane] = ws;
    }
    __syncthreads();
    int excl = ((wid == 0) ? 0 : wsum[wid - 1]) + s - v;
    if (i < NN) { g_rowstart[i] = excl; g_cursor[i] = excl; }
    if (tid == 0) g_bsum[blockIdx.x] = wsum[31];
}

// ---------------------------------------------------------------------------
// K3b: exclusive scan of the 49 block totals (single warp, 2 elems/lane)
// ---------------------------------------------------------------------------
__global__ void scanB_kernel() {
    int lane = threadIdx.x;
    int v0 = (lane < NB) ? g_bsum[lane] : 0;
    int v1 = (lane + 32 < NB) ? g_bsum[lane + 32] : 0;
    int s0 = v0;
    #pragma unroll
    for (int o = 1; o < 32; o <<= 1) {
        int t = __shfl_up_sync(0xffffffffu, s0, o);
        if (lane >= o) s0 += t;
    }
    int tot0 = __shfl_sync(0xffffffffu, s0, 31);
    int s1 = v1;
    #pragma unroll
    for (int o = 1; o < 32; o <<= 1) {
        int t = __shfl_up_sync(0xffffffffu, s1, o);
        if (lane >= o) s1 += t;
    }
    if (lane < NB) g_boff[lane] = s0 - v0;
    if (lane + 32 < NB) g_boff[lane + 32] = tot0 + s1 - v1;
}

// ---------------------------------------------------------------------------
// K4: fill CSR, 4 edges/thread. Final slot = local cursor + block offset.
// ---------------------------------------------------------------------------
__global__ void fill_kernel(const int* __restrict__ ei) {
    int t = blockIdx.x * blockDim.x + threadIdx.x;
    if (t < NE / 4) {
        int4 s = ((const int4*)ei)[t];
        int4 d = ((const int4*)(ei + NE))[t];
        int p0 = atomicAdd(&g_cursor[d.x], 1);
        int p1 = atomicAdd(&g_cursor[d.y], 1);
        int p2 = atomicAdd(&g_cursor[d.z], 1);
        int p3 = atomicAdd(&g_cursor[d.w], 1);
        g_csr[p0 + g_boff[d.x >> 10]] = s.x;
        g_csr[p1 + g_boff[d.y >> 10]] = s.y;
        g_csr[p2 + g_boff[d.z >> 10]] = s.z;
        g_csr[p3 + g_boff[d.w >> 10]] = s.w;
    }
}

// ---------------------------------------------------------------------------
// K5: gather-mean. Warp per row, lanes 0..23 own one float4 each.
// Unrolled x4 over neighbors (8 LDG.128 in flight / warp).
// ---------------------------------------------------------------------------
__global__ void agg_kernel(const float* __restrict__ x) {
    int warp = (blockIdx.x * blockDim.x + threadIdx.x) >> 5;
    int lane = threadIdx.x & 31;
    if (warp >= NN || lane >= 24) return;
    int rs  = g_rowstart[warp] + g_boff[warp >> 10];
    int deg = g_cnt[warp];
    float4 a0 = make_float4(0.f, 0.f, 0.f, 0.f);
    float4 a1 = make_float4(0.f, 0.f, 0.f, 0.f);
    int j = 0;
    for (; j + 4 <= deg; j += 4) {
        int s0 = g_csr[rs + j];
        int s1 = g_csr[rs + j + 1];
        int s2 = g_csr[rs + j + 2];
        int s3 = g_csr[rs + j + 3];
        float4 v0 = ((const float4*)(x + (long)s0 * DIN))[lane];
        float4 v1 = ((const float4*)(x + (long)s1 * DIN))[lane];
        float4 v2 = ((const float4*)(x + (long)s2 * DIN))[lane];
        float4 v3 = ((const float4*)(x + (long)s3 * DIN))[lane];
        a0.x += v0.x; a0.y += v0.y; a0.z += v0.z; a0.w += v0.w;
        a1.x += v1.x; a1.y += v1.y; a1.z += v1.z; a1.w += v1.w;
        a0.x += v2.x; a0.y += v2.y; a0.z += v2.z; a0.w += v2.w;
        a1.x += v3.x; a1.y += v3.y; a1.z += v3.z; a1.w += v3.w;
    }
    for (; j < deg; j++) {
        int s0 = g_csr[rs + j];
        float4 v0 = ((const float4*)(x + (long)s0 * DIN))[lane];
        a0.x += v0.x; a0.y += v0.y; a0.z += v0.z; a0.w += v0.w;
    }
    float inv = 1.0f / (float)max(deg, 1);
    a0.x = (a0.x + a1.x) * inv;
    a0.y = (a0.y + a1.y) * inv;
    a0.z = (a0.z + a1.z) * inv;
    a0.w = (a0.w + a1.w) * inv;
    ((float4*)(g_agg + (long)warp * DIN))[lane] = a0;
}

// ---------------------------------------------------------------------------
// K6: out = relu( agg @ Wl^T + bl + x @ Wr^T )   (packed fp32x2 FFMA)
// Same mapping as the 126us kernel (2 cols x 8 rows/thread, 32-row tiles,
// 64-col half per block, 3 CTAs/SM). NEW: next tile is prefetched into
// registers (6 float4 per array per thread) while computing the current
// tile, hiding the L2 staging latency without raising SMEM.
// ---------------------------------------------------------------------------
__device__ __forceinline__ unsigned long long ffma2_(unsigned long long a,
                                                     unsigned long long b,
                                                     unsigned long long c) {
    unsigned long long d;
    asm("fma.rn.f32x2 %0, %1, %2, %3;" : "=l"(d) : "l"(a), "l"(b), "l"(c));
    return d;
}

#define WPAD 100
#define SM_WL 0
#define SM_WR 6400
#define SM_X  12800
#define SM_A  15872
#define SM_FLOATS 18944   // 75776 bytes -> 3 CTAs/SM

__global__ void __launch_bounds__(128) gemm_kernel(
    const float* __restrict__ x, const float* __restrict__ Wl,
    const float* __restrict__ bl, const float* __restrict__ Wr,
    float* __restrict__ out) {
    extern __shared__ __align__(16) float sm[];
    float* sWl = sm + SM_WL;
    float* sWr = sm + SM_WR;
    float* sx  = sm + SM_X;
    float* sa  = sm + SM_A;

    int tid = threadIdx.x;
    int colbase = (blockIdx.x & 1) * 64;

    for (int i = tid; i < 64 * DIN; i += 128) {
        int c = i / DIN, k = i - c * DIN;
        sWl[c * WPAD + k] = Wl[(colbase + c) * DIN + k];
        sWr[c * WPAD + k] = Wr[(colbase + c) * DIN + k];
    }

    int ct = tid & 31;
    int rbase = (tid >> 5) * 8;
    int c0 = ct, c1 = ct + 32;
    float b0 = bl[colbase + c0];
    float b1 = bl[colbase + c1];

    // this thread's 6 staging slots (i = tid + j*128 over 768 float4/array)
    int srow[6], sq[6];
    #pragma unroll
    for (int j = 0; j < 6; j++) {
        int i = tid + j * 128;
        srow[j] = i / 24;
        sq[j] = i - srow[j] * 24;
    }

    const int NT = (NN + 31) / 32;  // 1563
    int stride = gridDim.x >> 1;
    int t = blockIdx.x >> 1;

    float4 rx[6], ra[6];
    if (t < NT) {
        #pragma unroll
        for (int j = 0; j < 6; j++) {
            int gr = t * 32 + srow[j]; if (gr >= NN) gr = NN - 1;
            rx[j] = ((const float4*)(x + (long)gr * DIN))[sq[j]];
            ra[j] = ((const float4*)(g_agg + (long)gr * DIN))[sq[j]];
        }
    }

    for (; t < NT; t += stride) {
        int row0 = t * 32;
        __syncthreads();   // prev tile compute done (weights staged on iter 0)
        #pragma unroll
        for (int j = 0; j < 6; j++) {
            ((float4*)(sx + srow[j] * DIN))[sq[j]] = rx[j];
            ((float4*)(sa + srow[j] * DIN))[sq[j]] = ra[j];
        }
        __syncthreads();

        // prefetch next tile into registers; LDG latency hidden by compute
        int tn = t + stride;
        if (tn < NT) {
            #pragma unroll
            for (int j = 0; j < 6; j++) {
                int gr = tn * 32 + srow[j]; if (gr >= NN) gr = NN - 1;
                rx[j] = ((const float4*)(x + (long)gr * DIN))[sq[j]];
                ra[j] = ((const float4*)(g_agg + (long)gr * DIN))[sq[j]];
            }
        }

        unsigned long long acc0[8], acc1[8];
        #pragma unroll
        for (int r = 0; r < 8; r++) { acc0[r] = 0ull; acc1[r] = 0ull; }

        #pragma unroll 4
        for (int k = 0; k < DIN; k += 4) {
            ulonglong2 wl0 = *(const ulonglong2*)(sWl + c0 * WPAD + k);
            ulonglong2 wl1 = *(const ulonglong2*)(sWl + c1 * WPAD + k);
            ulonglong2 wr0 = *(const ulonglong2*)(sWr + c0 * WPAD + k);
            ulonglong2 wr1 = *(const ulonglong2*)(sWr + c1 * WPAD + k);
            #pragma unroll
            for (int r = 0; r < 8; r++) {
                ulonglong2 av = *(const ulonglong2*)(sa + (rbase + r) * DIN + k);
                ulonglong2 xv = *(const ulonglong2*)(sx + (rbase + r) * DIN + k);
                acc0[r] = ffma2_(wl0.x, av.x, acc0[r]);
                acc0[r] = ffma2_(wl0.y, av.y, acc0[r]);
                acc0[r] = ffma2_(wr0.x, xv.x, acc0[r]);
                acc0[r] = ffma2_(wr0.y, xv.y, acc0[r]);
                acc1[r] = ffma2_(wl1.x, av.x, acc1[r]);
                acc1[r] = ffma2_(wl1.y, av.y, acc1[r]);
                acc1[r] = ffma2_(wr1.x, xv.x, acc1[r]);
                acc1[r] = ffma2_(wr1.y, xv.y, acc1[r]);
            }
        }

        #pragma unroll
        for (int r = 0; r < 8; r++) {
            int row = row0 + rbase + r;
            if (row < NN) {
                float l0 = __uint_as_float((unsigned)(acc0[r] & 0xffffffffull));
                float h0 = __uint_as_float((unsigned)(acc0[r] >> 32));
                float l1 = __uint_as_float((unsigned)(acc1[r] & 0xffffffffull));
                float h1 = __uint_as_float((unsigned)(acc1[r] >> 32));
                float v0 = l0 + h0 + b0;
                float v1 = l1 + h1 + b1;
                out[(long)row * DOUT + colbase + c0] = fmaxf(v0, 0.f);
                out[(long)row * DOUT + colbase + c1] = fmaxf(v1, 0.f);
            }
        }
    }
}

// ---------------------------------------------------------------------------
extern "C" void kernel_launch(void* const* d_in, const int* in_sizes, int n_in,
                              void* d_out, int out_size) {
    const float* x  = (const float*)d_in[0];
    const int*   ei = (const int*)d_in[1];
    const float* Wl = (const float*)d_in[2];
    const float* bl = (const float*)d_in[3];
    const float* Wr = (const float*)d_in[4];
    float* out = (float*)d_out;

    cudaFuncSetAttribute(gemm_kernel, cudaFuncAttributeMaxDynamicSharedMemorySize,
                         SM_FLOATS * (int)sizeof(float));

    zero_cnt_kernel<<<(NN + 255) / 256, 256>>>();
    count_kernel<<<(NE / 4 + 255) / 256, 256>>>(ei);
    scanA_kernel<<<NB, 1024>>>();
    scanB_kernel<<<1, 32>>>();
    fill_kernel<<<(NE / 4 + 255) / 256, 256>>>(ei);
    agg_kernel<<<(NN * 32 + 255) / 256, 256>>>(x);
    gemm_kernel<<<444, 128, SM_FLOATS * sizeof(float)>>>(x, Wl, bl, Wr, out);
}